// round 9
// baseline (speedup 1.0000x reference)
#include <cuda_runtime.h>
#include <cuda_fp16.h>
#include <cstdint>

// Problem constants
#define BB   8
#define CC   1024
#define HH   64
#define WW   64
#define NHD  16
#define HD   64
#define HWP  4096
#define CHW  (CC * HWP)
#define EPSB 1e-3f

// Scale folding: W stored x2^14, X stored x2^10, epilogue multiplies 2^-24.
#define WSCALE 16384.0f
#define XSCALE 1024.0f
#define INV_S  5.9604644775390625e-8f   // 2^-24

// GEMM tiling: CTA 128x256, warp tile 64x64 (2x4 warps), BK=64, 2 stages
#define BM   128
#define BN   256
#define BKE  64              // fp16 K elems per stage
#define LDT  72              // padded SMEM row (elems) = 144B, conflict-free
#define NKT  (CC / BKE)      // 16 iterations

#define ATILE_B  (BM * LDT * 2)           // 18432 B
#define BTILE_B  (BN * LDT * 2)           // 36864 B
#define STAGE_B  (ATILE_B + BTILE_B)      // 55296 B
#define SMEM_TOT (2 * STAGE_B)            // 110592 B -> 1 CTA/SM

// dwconv fused kernel
#define DWC  8
#define DW_SMEM (DWC * HWP * 4)           // 131072 B

// ---------------------------------------------------------------------------
// Scratch (device globals; no allocation allowed)
// ---------------------------------------------------------------------------
__device__ float g_y1[BB * CHW];
__device__ float g_y2[BB * CHW];
__device__ __half g_w1h[CC * CC];
__device__ __half g_w3h[CC * CC];
__device__ __half g_bh[BB * HWP * CC];   // transposed activations [b][p][ci]

// ---------------------------------------------------------------------------
// PTX helpers
// ---------------------------------------------------------------------------
__device__ __forceinline__ uint32_t smem_u32(const void* p) {
    uint32_t a;
    asm("{ .reg .u64 t; cvta.to.shared.u64 t, %1; cvt.u32.u64 %0, t; }" : "=r"(a) : "l"(p));
    return a;
}
__device__ __forceinline__ void cp_async16(uint32_t saddr, const void* gaddr) {
    asm volatile("cp.async.cg.shared.global [%0], [%1], 16;" :: "r"(saddr), "l"(gaddr));
}
__device__ __forceinline__ void cp_commit() {
    asm volatile("cp.async.commit_group;" ::: "memory");
}
template <int N>
__device__ __forceinline__ void cp_wait() {
    asm volatile("cp.async.wait_group %0;" :: "n"(N) : "memory");
}
__device__ __forceinline__ void ldmx4(uint32_t* r, uint32_t addr) {
    asm volatile("ldmatrix.sync.aligned.m8n8.x4.shared.b16 {%0,%1,%2,%3}, [%4];"
                 : "=r"(r[0]), "=r"(r[1]), "=r"(r[2]), "=r"(r[3]) : "r"(addr));
}
__device__ __forceinline__ void mma16816(float* c, const uint32_t* a,
                                         uint32_t b0, uint32_t b1) {
    asm volatile(
        "mma.sync.aligned.m16n8k16.row.col.f32.f16.f16.f32 "
        "{%0,%1,%2,%3}, {%4,%5,%6,%7}, {%8,%9}, {%0,%1,%2,%3};"
        : "+f"(c[0]), "+f"(c[1]), "+f"(c[2]), "+f"(c[3])
        : "r"(a[0]), "r"(a[1]), "r"(a[2]), "r"(a[3]), "r"(b0), "r"(b1));
}

// ---------------------------------------------------------------------------
// Converters
// ---------------------------------------------------------------------------
__global__ void convert_w_kernel(const float* __restrict__ W,
                                 __half* __restrict__ Wh)
{
    int i = blockIdx.x * blockDim.x + threadIdx.x;
    if (i < CC * CC) Wh[i] = __float2half_rn(W[i] * WSCALE);
}

// Transpose+convert: X fp32 [b][ci][p] -> fp16 [b][p][ci], scaled by XSCALE.
__global__ __launch_bounds__(256)
void transpose_cvt_kernel(const float* __restrict__ X,
                          __half* __restrict__ Th)
{
    __shared__ float t[64][33];
    const int p0 = blockIdx.x * 32;
    const int c0 = blockIdx.y * 64;
    const int b  = blockIdx.z;
    const int tid = threadIdx.x;

    const float* Xb = X + (size_t)b * CHW;
#pragma unroll
    for (int j = 0; j < 8; j++) {
        int i = j * 256 + tid;
        int r = i >> 5, cl = i & 31;
        t[r][cl] = Xb[(size_t)(c0 + r) * HWP + p0 + cl];
    }
    __syncthreads();

    __half* Tp = Th + (size_t)b * HWP * CC;
    const int cp = tid & 31;
#pragma unroll
    for (int j = 0; j < 4; j++) {
        int p = (tid >> 5) + j * 8;
        __half2 v = __floats2half2_rn(t[2 * cp][p] * XSCALE,
                                      t[2 * cp + 1][p] * XSCALE);
        *(__half2*)&Tp[(size_t)(p0 + p) * CC + c0 + 2 * cp] = v;
    }
}

// ---------------------------------------------------------------------------
// Warp-MMA fp16 GEMM + BN + SiLU (+residual). 64x64 warp tile, 2-stage.
// ---------------------------------------------------------------------------
__global__ __launch_bounds__(256, 1)
void gemm_mma_kernel(const __half* __restrict__ Ah,
                     const __half* __restrict__ Bh_,
                     const float* __restrict__ gam,
                     const float* __restrict__ bet,
                     const float* __restrict__ mu,
                     const float* __restrict__ var,
                     const float* __restrict__ res,
                     float* __restrict__ out)
{
    extern __shared__ char smem[];
    const uint32_t sb = smem_u32(smem);

    const int tid  = threadIdx.x;
    const int warp = tid >> 5, lane = tid & 31;
    const int warp_m = warp >> 2;          // 0..1 -> 64 rows each
    const int warp_n = warp & 3;           // 0..3 -> 64 cols each

    const int n0 = blockIdx.x * BN;
    const int m0 = blockIdx.y * BM;
    const int bz = blockIdx.z;
    const __half* Bh = Bh_ + (size_t)bz * HWP * CC;

    float acc[4][8][4];
#pragma unroll
    for (int i = 0; i < 4; i++)
#pragma unroll
        for (int j = 0; j < 8; j++)
#pragma unroll
            for (int q = 0; q < 4; q++) acc[i][j][q] = 0.f;

    // hoisted staging addresses
    //   A tile: 128 rows x 8 chunks(16B) = 1024 chunks, 4/thread
    //   B tile: 256 rows x 8 chunks(16B) = 2048 chunks, 8/thread
    const __half* apt[4];
    uint32_t aoff[4];
#pragma unroll
    for (int j = 0; j < 4; j++) {
        int rc = tid + j * 256;
        int row = rc >> 3, c = (rc & 7) * 8;
        aoff[j] = (row * LDT + c) * 2;
        apt[j] = Ah + (size_t)(m0 + row) * CC + c;
    }
    const __half* bpt[8];
    uint32_t boff[8];
#pragma unroll
    for (int j = 0; j < 8; j++) {
        int rc = tid + j * 256;
        int row = rc >> 3, c = (rc & 7) * 8;
        boff[j] = (row * LDT + c) * 2;
        bpt[j] = Bh + (size_t)(n0 + row) * CC + c;
    }

    auto stage = [&](int it) {
        const uint32_t st = sb + (it & 1) * STAGE_B;
        const int kt = it * BKE;
#pragma unroll
        for (int j = 0; j < 4; j++)
            cp_async16(st + aoff[j], apt[j] + kt);
#pragma unroll
        for (int j = 0; j < 8; j++)
            cp_async16(st + ATILE_B + boff[j], bpt[j] + kt);
        cp_commit();
    };

    const int lr = lane & 15;
    const int lh = (lane >> 4) * 8;

    stage(0);

    for (int it = 0; it < NKT; it++) {
        if (it + 1 < NKT) {
            stage(it + 1);
            cp_wait<1>();
        } else {
            cp_wait<0>();
        }
        __syncthreads();

        const uint32_t st = sb + (it & 1) * STAGE_B;
#pragma unroll
        for (int kh = 0; kh < 4; kh++) {
            const int k16 = kh * 16;
            uint32_t af[4][4];
#pragma unroll
            for (int mt = 0; mt < 4; mt++)
                ldmx4(af[mt], st + ((warp_m * 64 + mt * 16 + lr) * LDT + k16 + lh) * 2);
            uint32_t bf[4][4];
#pragma unroll
            for (int nt2 = 0; nt2 < 4; nt2++)
                ldmx4(bf[nt2], st + ATILE_B +
                      ((warp_n * 64 + nt2 * 16 + lr) * LDT + k16 + lh) * 2);
#pragma unroll
            for (int mt = 0; mt < 4; mt++)
#pragma unroll
                for (int nt = 0; nt < 8; nt++)
                    mma16816(acc[mt][nt], af[mt],
                             bf[nt >> 1][nt & 1], bf[nt >> 1][(nt & 1) + 2]);
        }
        __syncthreads();
    }

    // epilogue: BN + SiLU (+res), 2^-24 folded into sc
    const int qrow = lane >> 2;
    const int qcol = (lane & 3) * 2;
#pragma unroll
    for (int mt = 0; mt < 4; mt++) {
#pragma unroll
        for (int half = 0; half < 2; half++) {
            const int co = m0 + warp_m * 64 + mt * 16 + qrow + half * 8;
            const float sc0 = gam[co] * rsqrtf(var[co] + EPSB);
            const float bi = bet[co] - mu[co] * sc0;
            const float sc = sc0 * INV_S;
            float* orow = out + (size_t)bz * CHW + (size_t)co * HWP + n0 + warp_n * 64;
            const float* rrow = res ? res + (size_t)bz * CHW + (size_t)co * HWP
                                        + n0 + warp_n * 64
                                    : nullptr;
#pragma unroll
            for (int nt = 0; nt < 8; nt++) {
                const int nn = nt * 8 + qcol;
                float y0 = acc[mt][nt][half * 2 + 0] * sc + bi;
                float y1 = acc[mt][nt][half * 2 + 1] * sc + bi;
                y0 = y0 * (1.f / (1.f + __expf(-y0)));
                y1 = y1 * (1.f / (1.f + __expf(-y1)));
                if (rrow) { y0 += rrow[nn]; y1 += rrow[nn + 1]; }
                *(float2*)&orow[nn] = make_float2(y0, y1);
            }
        }
    }
}

// ---------------------------------------------------------------------------
// K2: per-(b,nh,h) softmax-attention (fp32)
// ---------------------------------------------------------------------------
__global__ __launch_bounds__(256)
void attn_kernel(const float* __restrict__ Y1, float* __restrict__ Y2)
{
    const int bid = blockIdx.x;
    const int h  = bid & 63;
    const int nh = (bid >> 6) & 15;
    const int b  = bid >> 10;

    const float* basep = Y1 + (size_t)b * CHW + (size_t)(nh * HD) * HWP + h * WW;

    __shared__ float A[64][65];
    __shared__ float P[64][65];

    const int tid = threadIdx.x;
#pragma unroll
    for (int it = 0; it < 16; it++) {
        int idx = it * 256 + tid;
        int k = idx >> 6, w = idx & 63;
        A[w][k] = basep[(size_t)k * HWP + w];
    }
    __syncthreads();

    const int lane = tid & 31, warp = tid >> 5;
#pragma unroll
    for (int r = 0; r < 8; r++) {
        int row = warp * 8 + r;
        float x0 = A[row][lane], x1 = A[row][lane + 32];
        float mx = fmaxf(x0, x1);
#pragma unroll
        for (int o = 16; o > 0; o >>= 1) mx = fmaxf(mx, __shfl_xor_sync(0xffffffffu, mx, o));
        float e0 = __expf(x0 - mx), e1 = __expf(x1 - mx);
        float s = e0 + e1;
#pragma unroll
        for (int o = 16; o > 0; o >>= 1) s += __shfl_xor_sync(0xffffffffu, s, o);
        float inv = 1.f / s;
        P[row][lane]      = e0 * inv;
        P[row][lane + 32] = e1 * inv;
    }
    __syncthreads();

    const int tx = tid & 15;
    const int ty = tid >> 4;
    float accv[4][4] = {};
#pragma unroll 4
    for (int k = 0; k < 64; k++) {
        float pv[4], av[4];
#pragma unroll
        for (int i = 0; i < 4; i++) {
            pv[i] = P[ty * 4 + i][k];
            av[i] = A[tx * 4 + i][k];
        }
#pragma unroll
        for (int i = 0; i < 4; i++)
#pragma unroll
            for (int j = 0; j < 4; j++)
                accv[i][j] = fmaf(pv[i], av[j], accv[i][j]);
    }
    __syncthreads();

#pragma unroll
    for (int i = 0; i < 4; i++)
#pragma unroll
        for (int j = 0; j < 4; j++)
            A[tx * 4 + j][ty * 4 + i] = accv[i][j];
    __syncthreads();

    float* outb = Y2 + (size_t)b * CHW + (size_t)(nh * HD) * HWP + h * WW;
#pragma unroll
    for (int it = 0; it < 16; it++) {
        int idx = it * 256 + tid;
        int v = idx >> 6, w = idx & 63;
        outb[(size_t)v * HWP + w] = A[v][w];
    }
}

// ---------------------------------------------------------------------------
// K3 fused: depthwise 3x3 + BN + SiLU + transpose + fp16 convert.
// ---------------------------------------------------------------------------
__global__ __launch_bounds__(256)
void dwconv_t_kernel(const float* __restrict__ X,
                     const float* __restrict__ W2,
                     const float* __restrict__ gam,
                     const float* __restrict__ bet,
                     const float* __restrict__ mu,
                     const float* __restrict__ var,
                     __half* __restrict__ Th)
{
    extern __shared__ float S[];
    const int c0 = blockIdx.x * DWC;
    const int b  = blockIdx.y;
    const int tid = threadIdx.x;

    const float4* src = (const float4*)(X + ((size_t)b * CC + c0) * HWP);
    float4* dst = (float4*)S;
#pragma unroll
    for (int j = 0; j < 32; j++)
        dst[j * 256 + tid] = src[j * 256 + tid];

    float w[DWC][9], sc[DWC], bi[DWC];
#pragma unroll
    for (int ch = 0; ch < DWC; ch++) {
        const int c = c0 + ch;
#pragma unroll
        for (int k = 0; k < 9; k++) w[ch][k] = W2[c * 9 + k];
        const float s0 = gam[c] * rsqrtf(var[c] + EPSB);
        sc[ch] = s0;
        bi[ch] = bet[c] - mu[c] * s0;
    }
    __syncthreads();

    __half* outp = Th + (size_t)b * HWP * CC + c0;
#pragma unroll 2
    for (int k = 0; k < 16; k++) {
        const int p = k * 256 + tid;
        const int y = p >> 6, x = p & 63;
        int off[9];
        float msk[9];
#pragma unroll
        for (int dy = 0; dy < 3; dy++)
#pragma unroll
            for (int dx = 0; dx < 3; dx++) {
                int yy = y + dy - 1, xx = x + dx - 1;
                bool ok = (unsigned)yy < 64u && (unsigned)xx < 64u;
                off[dy * 3 + dx] = ok ? yy * 64 + xx : 0;
                msk[dy * 3 + dx] = ok ? 1.f : 0.f;
            }
        __half h8[DWC];
#pragma unroll
        for (int ch = 0; ch < DWC; ch++) {
            const float* pl = S + ch * HWP;
            float s = 0.f;
#pragma unroll
            for (int t = 0; t < 9; t++)
                s = fmaf(w[ch][t], pl[off[t]] * msk[t], s);
            s = s * sc[ch] + bi[ch];
            s = s * (1.f / (1.f + __expf(-s)));
            h8[ch] = __float2half_rn(s * XSCALE);
        }
        *(uint4*)&outp[(size_t)p * CC] = *(uint4*)h8;
    }
}

// ---------------------------------------------------------------------------
// Launch. setup_inputs() dict order:
//   0:x 1:w1 2:w2 3:w3 4:g1 5:b1 6:m1 7:v1 8:g2 9:b2 10:m2 11:v2 12:g3 13:b3 14:m3 15:v3
// ---------------------------------------------------------------------------
extern "C" void kernel_launch(void* const* d_in, const int* in_sizes, int n_in,
                              void* d_out, int out_size)
{
    const float* x  = (const float*)d_in[0];
    const float* w1 = (const float*)d_in[1];
    const float* w2 = (const float*)d_in[2];
    const float* w3 = (const float*)d_in[3];
    const float* g1 = (const float*)d_in[4];
    const float* b1 = (const float*)d_in[5];
    const float* m1 = (const float*)d_in[6];
    const float* v1 = (const float*)d_in[7];
    const float* g2 = (const float*)d_in[8];
    const float* b2 = (const float*)d_in[9];
    const float* m2 = (const float*)d_in[10];
    const float* v2 = (const float*)d_in[11];
    const float* g3 = (const float*)d_in[12];
    const float* b3 = (const float*)d_in[13];
    const float* m3 = (const float*)d_in[14];
    const float* v3 = (const float*)d_in[15];
    float* out = (float*)d_out;

    if (!(in_sizes[1] == CC * CC && in_sizes[2] == CC * 9 && in_sizes[3] == CC * CC)) {
        const float* big[2] = {nullptr, nullptr}; int nbig = 0;
        const float* small9216 = nullptr;
        const float* perch[12]; int nper = 0;
        for (int i = 1; i < n_in; i++) {
            if (in_sizes[i] == CC * CC && nbig < 2) big[nbig++] = (const float*)d_in[i];
            else if (in_sizes[i] == CC * 9) small9216 = (const float*)d_in[i];
            else if (in_sizes[i] == CC && nper < 12) perch[nper++] = (const float*)d_in[i];
        }
        w1 = big[0]; w3 = big[1]; w2 = small9216;
        g1 = perch[0]; b1 = perch[1]; m1 = perch[2];  v1 = perch[3];
        g2 = perch[4]; b2 = perch[5]; m2 = perch[6];  v2 = perch[7];
        g3 = perch[8]; b3 = perch[9]; m3 = perch[10]; v3 = perch[11];
    }

    float *p_y1, *p_y2;
    __half *p_w1h, *p_w3h, *p_bh;
    cudaGetSymbolAddress((void**)&p_y1, g_y1);
    cudaGetSymbolAddress((void**)&p_y2, g_y2);
    cudaGetSymbolAddress((void**)&p_w1h, g_w1h);
    cudaGetSymbolAddress((void**)&p_w3h, g_w3h);
    cudaGetSymbolAddress((void**)&p_bh, g_bh);

    cudaFuncSetAttribute(gemm_mma_kernel,
                         cudaFuncAttributeMaxDynamicSharedMemorySize, SMEM_TOT);
    cudaFuncSetAttribute(dwconv_t_kernel,
                         cudaFuncAttributeMaxDynamicSharedMemorySize, DW_SMEM);

    dim3 tgrid(HWP / 32, CC / 64, BB);
    dim3 ggrid(HWP / BN, CC / BM, BB);     // (16, 8, 8)
    dim3 dgrid(CC / DWC, BB);              // (128, 8)

    convert_w_kernel<<<(CC * CC + 511) / 512, 512>>>(w1, p_w1h);
    convert_w_kernel<<<(CC * CC + 511) / 512, 512>>>(w3, p_w3h);
    transpose_cvt_kernel<<<tgrid, 256>>>(x, p_bh);
    gemm_mma_kernel<<<ggrid, 256, SMEM_TOT>>>(p_w1h, p_bh,
                                              g1, b1, m1, v1, nullptr, p_y1);
    attn_kernel<<<BB * NHD * HH, 256>>>(p_y1, p_y2);
    dwconv_t_kernel<<<dgrid, 256, DW_SMEM>>>(p_y2, w2, g2, b2, m2, v2, p_bh);
    gemm_mma_kernel<<<ggrid, 256, SMEM_TOT>>>(p_w3h, p_bh,
                                              g3, b3, m3, v3, x, out);
}

// round 10
// speedup vs baseline: 1.3468x; 1.3468x over previous
#include <cuda_runtime.h>
#include <cuda_fp16.h>
#include <cstdint>

// Problem constants
#define BB   8
#define CC   1024
#define HH   64
#define WW   64
#define NHD  16
#define HD   64
#define HWP  4096
#define CHW  (CC * HWP)
#define EPSB 1e-3f

// Scale folding: W stored x2^14, X stored x2^10, epilogue multiplies 2^-24.
#define WSCALE 16384.0f
#define XSCALE 1024.0f
#define INV_S  5.9604644775390625e-8f   // 2^-24

// GEMM tiling (R8-proven: 128x128, BK=64, 2-stage, 2 CTAs/SM)
#define BM   128
#define BN   128
#define BKE  64
#define LDT  72              // padded SMEM row (elems) = 144B
#define NKT  (CC / BKE)      // 16

#define TILE_B   (128 * LDT * 2)          // 18432 B
#define STAGE_B  (2 * TILE_B)
#define SMEM_TOT (2 * STAGE_B)            // 73728 B -> 2 CTAs/SM

// dwconv fused kernel
#define DWC  8
#define DW_SMEM (DWC * HWP * 4)           // 131072 B

// attention
#define LDP  72              // fp16 row pad for ldmatrix tiles

// ---------------------------------------------------------------------------
// Scratch (device globals)
// ---------------------------------------------------------------------------
__device__ float g_y1[BB * CHW];
__device__ float g_y2[BB * CHW];
__device__ __half g_w1h[CC * CC];
__device__ __half g_w3h[CC * CC];
__device__ __half g_bh[BB * HWP * CC];   // transposed activations [b][p][ci]

// ---------------------------------------------------------------------------
// PTX helpers
// ---------------------------------------------------------------------------
__device__ __forceinline__ uint32_t smem_u32(const void* p) {
    uint32_t a;
    asm("{ .reg .u64 t; cvta.to.shared.u64 t, %1; cvt.u32.u64 %0, t; }" : "=r"(a) : "l"(p));
    return a;
}
__device__ __forceinline__ void cp_async16(uint32_t saddr, const void* gaddr) {
    asm volatile("cp.async.cg.shared.global [%0], [%1], 16;" :: "r"(saddr), "l"(gaddr));
}
__device__ __forceinline__ void cp_commit() {
    asm volatile("cp.async.commit_group;" ::: "memory");
}
template <int N>
__device__ __forceinline__ void cp_wait() {
    asm volatile("cp.async.wait_group %0;" :: "n"(N) : "memory");
}
__device__ __forceinline__ void ldmx4(uint32_t* r, uint32_t addr) {
    asm volatile("ldmatrix.sync.aligned.m8n8.x4.shared.b16 {%0,%1,%2,%3}, [%4];"
                 : "=r"(r[0]), "=r"(r[1]), "=r"(r[2]), "=r"(r[3]) : "r"(addr));
}
__device__ __forceinline__ void mma16816(float* c, const uint32_t* a,
                                         uint32_t b0, uint32_t b1) {
    asm volatile(
        "mma.sync.aligned.m16n8k16.row.col.f32.f16.f16.f32 "
        "{%0,%1,%2,%3}, {%4,%5,%6,%7}, {%8,%9}, {%0,%1,%2,%3};"
        : "+f"(c[0]), "+f"(c[1]), "+f"(c[2]), "+f"(c[3])
        : "r"(a[0]), "r"(a[1]), "r"(a[2]), "r"(a[3]), "r"(b0), "r"(b1));
}

// ---------------------------------------------------------------------------
// Converters
// ---------------------------------------------------------------------------
__global__ void convert_w2_kernel(const float* __restrict__ W1,
                                  const float* __restrict__ W3,
                                  __half* __restrict__ O1,
                                  __half* __restrict__ O3)
{
    int i = blockIdx.x * blockDim.x + threadIdx.x;
    if (i < CC * CC) {
        O1[i] = __float2half_rn(W1[i] * WSCALE);
        O3[i] = __float2half_rn(W3[i] * WSCALE);
    }
}

// Transpose+convert: X fp32 [b][ci][p] -> fp16 [b][p][ci], scaled by XSCALE.
__global__ __launch_bounds__(256)
void transpose_cvt_kernel(const float* __restrict__ X,
                          __half* __restrict__ Th)
{
    __shared__ float t[64][33];
    const int p0 = blockIdx.x * 32;
    const int c0 = blockIdx.y * 64;
    const int b  = blockIdx.z;
    const int tid = threadIdx.x;

    const float* Xb = X + (size_t)b * CHW;
#pragma unroll
    for (int j = 0; j < 8; j++) {
        int i = j * 256 + tid;
        int r = i >> 5, cl = i & 31;
        t[r][cl] = Xb[(size_t)(c0 + r) * HWP + p0 + cl];
    }
    __syncthreads();

    __half* Tp = Th + (size_t)b * HWP * CC;
    const int cp = tid & 31;
#pragma unroll
    for (int j = 0; j < 4; j++) {
        int p = (tid >> 5) + j * 8;
        __half2 v = __floats2half2_rn(t[2 * cp][p] * XSCALE,
                                      t[2 * cp + 1][p] * XSCALE);
        *(__half2*)&Tp[(size_t)(p0 + p) * CC + c0 + 2 * cp] = v;
    }
}

// ---------------------------------------------------------------------------
// Warp-MMA fp16 GEMM + BN + SiLU (+residual). R8 config.
// ---------------------------------------------------------------------------
__global__ __launch_bounds__(256, 2)
void gemm_mma_kernel(const __half* __restrict__ Ah,
                     const __half* __restrict__ Bh_,
                     const float* __restrict__ gam,
                     const float* __restrict__ bet,
                     const float* __restrict__ mu,
                     const float* __restrict__ var,
                     const float* __restrict__ res,
                     float* __restrict__ out)
{
    extern __shared__ char smem[];
    const uint32_t sb = smem_u32(smem);

    const int tid  = threadIdx.x;
    const int warp = tid >> 5, lane = tid & 31;
    const int warp_m = warp >> 2;
    const int warp_n = warp & 3;

    const int n0 = blockIdx.x * BN;
    const int m0 = blockIdx.y * BM;
    const int bz = blockIdx.z;
    const __half* Bh = Bh_ + (size_t)bz * HWP * CC;

    float acc[4][4][4];
#pragma unroll
    for (int i = 0; i < 4; i++)
#pragma unroll
        for (int j = 0; j < 4; j++)
#pragma unroll
            for (int q = 0; q < 4; q++) acc[i][j][q] = 0.f;

    const __half* apt[4];
    const __half* bpt[4];
    uint32_t soff[4];
#pragma unroll
    for (int j = 0; j < 4; j++) {
        int rc = tid + j * 256;
        int row = rc >> 3, c = (rc & 7) * 8;
        soff[j] = (row * LDT + c) * 2;
        apt[j] = Ah + (size_t)(m0 + row) * CC + c;
        bpt[j] = Bh + (size_t)(n0 + row) * CC + c;
    }

    auto stage = [&](int it) {
        const uint32_t st = sb + (it & 1) * STAGE_B;
        const int kt = it * BKE;
#pragma unroll
        for (int j = 0; j < 4; j++) {
            cp_async16(st + soff[j], apt[j] + kt);
            cp_async16(st + TILE_B + soff[j], bpt[j] + kt);
        }
        cp_commit();
    };

    const int lr = lane & 15;
    const int lh = (lane >> 4) * 8;

    stage(0);

    for (int it = 0; it < NKT; it++) {
        if (it + 1 < NKT) {
            stage(it + 1);
            cp_wait<1>();
        } else {
            cp_wait<0>();
        }
        __syncthreads();

        const uint32_t st = sb + (it & 1) * STAGE_B;
#pragma unroll
        for (int kh = 0; kh < 4; kh++) {
            const int k16 = kh * 16;
            uint32_t af[4][4];
#pragma unroll
            for (int mt = 0; mt < 4; mt++)
                ldmx4(af[mt], st + ((warp_m * 64 + mt * 16 + lr) * LDT + k16 + lh) * 2);
            uint32_t bf[2][4];
#pragma unroll
            for (int nt2 = 0; nt2 < 2; nt2++)
                ldmx4(bf[nt2], st + TILE_B +
                      ((warp_n * 32 + nt2 * 16 + lr) * LDT + k16 + lh) * 2);
#pragma unroll
            for (int mt = 0; mt < 4; mt++)
#pragma unroll
                for (int nt = 0; nt < 4; nt++)
                    mma16816(acc[mt][nt], af[mt],
                             bf[nt >> 1][nt & 1], bf[nt >> 1][(nt & 1) + 2]);
        }
        __syncthreads();
    }

    const int qrow = lane >> 2;
    const int qcol = (lane & 3) * 2;
#pragma unroll
    for (int mt = 0; mt < 4; mt++) {
#pragma unroll
        for (int half = 0; half < 2; half++) {
            const int co = m0 + warp_m * 64 + mt * 16 + qrow + half * 8;
            const float sc0 = gam[co] * rsqrtf(var[co] + EPSB);
            const float bi = bet[co] - mu[co] * sc0;
            const float sc = sc0 * INV_S;
            float* orow = out + (size_t)bz * CHW + (size_t)co * HWP + n0 + warp_n * 32;
            const float* rrow = res ? res + (size_t)bz * CHW + (size_t)co * HWP
                                        + n0 + warp_n * 32
                                    : nullptr;
#pragma unroll
            for (int nt = 0; nt < 4; nt++) {
                const int nn = nt * 8 + qcol;
                float y0 = acc[mt][nt][half * 2 + 0] * sc + bi;
                float y1 = acc[mt][nt][half * 2 + 1] * sc + bi;
                y0 = y0 * (1.f / (1.f + __expf(-y0)));
                y1 = y1 * (1.f / (1.f + __expf(-y1)));
                if (rrow) { y0 += rrow[nn]; y1 += rrow[nn + 1]; }
                *(float2*)&orow[nn] = make_float2(y0, y1);
            }
        }
    }
}

// ---------------------------------------------------------------------------
// K2: per-(b,nh,h) softmax-attention. Softmax fp32; AV matmul via fp16 MMA.
//   att[w][v] = sum_k P[w][k] * A[v][k]  ->  C = P(row) x A(col), both [row][k]
// ---------------------------------------------------------------------------
__global__ __launch_bounds__(256)
void attn_kernel(const float* __restrict__ Y1, float* __restrict__ Y2)
{
    const int bid = blockIdx.x;
    const int h  = bid & 63;
    const int nh = (bid >> 6) & 15;
    const int b  = bid >> 10;

    const float* basep = Y1 + (size_t)b * CHW + (size_t)(nh * HD) * HWP + h * WW;

    __shared__ float Af[64][65];
    __shared__ __half Ph[64][LDP];
    __shared__ __half Ahh[64][LDP];

    const int tid = threadIdx.x;
    const int lane = tid & 31, warp = tid >> 5;

#pragma unroll
    for (int it = 0; it < 16; it++) {
        int idx = it * 256 + tid;
        int k = idx >> 6, w = idx & 63;
        Af[w][k] = basep[(size_t)k * HWP + w];
    }
    __syncthreads();

    // A -> fp16 (B operand of MMA)
#pragma unroll
    for (int it = 0; it < 16; it++) {
        int idx = it * 256 + tid;
        int w = idx >> 6, k = idx & 63;
        Ahh[w][k] = __float2half_rn(Af[w][k]);
    }

    // softmax rows (fp32), P -> fp16
#pragma unroll
    for (int r = 0; r < 8; r++) {
        int row = warp * 8 + r;
        float x0 = Af[row][lane], x1 = Af[row][lane + 32];
        float mx = fmaxf(x0, x1);
#pragma unroll
        for (int o = 16; o > 0; o >>= 1) mx = fmaxf(mx, __shfl_xor_sync(0xffffffffu, mx, o));
        float e0 = __expf(x0 - mx), e1 = __expf(x1 - mx);
        float s = e0 + e1;
#pragma unroll
        for (int o = 16; o > 0; o >>= 1) s += __shfl_xor_sync(0xffffffffu, s, o);
        float inv = 1.f / s;
        Ph[row][lane]      = __float2half_rn(e0 * inv);
        Ph[row][lane + 32] = __float2half_rn(e1 * inv);
    }
    __syncthreads();

    // MMA: warp tile 16(m=w) x 32(n=v), K=64
    const uint32_t ph = smem_u32(Ph);
    const uint32_t ah = smem_u32(Ahh);
    const int m0 = (warp & 3) * 16;
    const int nw0 = (warp >> 2) * 32;
    const int lr = lane & 15;
    const int lh = (lane >> 4) * 8;

    float acc[4][4];
#pragma unroll
    for (int i = 0; i < 4; i++)
#pragma unroll
        for (int q = 0; q < 4; q++) acc[i][q] = 0.f;

#pragma unroll
    for (int kh = 0; kh < 4; kh++) {
        const int k16 = kh * 16;
        uint32_t a[4];
        ldmx4(a, ph + ((m0 + lr) * LDP + k16 + lh) * 2);
        uint32_t bf[2][4];
#pragma unroll
        for (int g = 0; g < 2; g++)
            ldmx4(bf[g], ah + ((nw0 + g * 16 + lr) * LDP + k16 + lh) * 2);
#pragma unroll
        for (int nt = 0; nt < 4; nt++)
            mma16816(acc[nt], a, bf[nt >> 1][nt & 1], bf[nt >> 1][(nt & 1) + 2]);
    }
    __syncthreads();   // done reading Af (as smem source for Ahh) / reuse Af

    // write transposed: Af[v][w] = att[w][v]
    const int qrow = lane >> 2;
    const int qcol = (lane & 3) * 2;
#pragma unroll
    for (int nt = 0; nt < 4; nt++)
#pragma unroll
        for (int half = 0; half < 2; half++) {
            int w = m0 + qrow + half * 8;
            int v = nw0 + nt * 8 + qcol;
            Af[v][w]     = acc[nt][half * 2 + 0];
            Af[v + 1][w] = acc[nt][half * 2 + 1];
        }
    __syncthreads();

    float* outb = Y2 + (size_t)b * CHW + (size_t)(nh * HD) * HWP + h * WW;
#pragma unroll
    for (int it = 0; it < 16; it++) {
        int idx = it * 256 + tid;
        int v = idx >> 6, w = idx & 63;
        outb[(size_t)v * HWP + w] = Af[v][w];
    }
}

// ---------------------------------------------------------------------------
// K3 fused: depthwise 3x3 + BN + SiLU + transpose + fp16 convert.
// ---------------------------------------------------------------------------
__global__ __launch_bounds__(256)
void dwconv_t_kernel(const float* __restrict__ X,
                     const float* __restrict__ W2,
                     const float* __restrict__ gam,
                     const float* __restrict__ bet,
                     const float* __restrict__ mu,
                     const float* __restrict__ var,
                     __half* __restrict__ Th)
{
    extern __shared__ float S[];
    const int c0 = blockIdx.x * DWC;
    const int b  = blockIdx.y;
    const int tid = threadIdx.x;

    const float4* src = (const float4*)(X + ((size_t)b * CC + c0) * HWP);
    float4* dst = (float4*)S;
#pragma unroll
    for (int j = 0; j < 32; j++)
        dst[j * 256 + tid] = src[j * 256 + tid];

    float w[DWC][9], sc[DWC], bi[DWC];
#pragma unroll
    for (int ch = 0; ch < DWC; ch++) {
        const int c = c0 + ch;
#pragma unroll
        for (int k = 0; k < 9; k++) w[ch][k] = W2[c * 9 + k];
        const float s0 = gam[c] * rsqrtf(var[c] + EPSB);
        sc[ch] = s0;
        bi[ch] = bet[c] - mu[c] * s0;
    }
    __syncthreads();

    __half* outp = Th + (size_t)b * HWP * CC + c0;
#pragma unroll 2
    for (int k = 0; k < 16; k++) {
        const int p = k * 256 + tid;
        const int y = p >> 6, x = p & 63;
        int off[9];
        float msk[9];
#pragma unroll
        for (int dy = 0; dy < 3; dy++)
#pragma unroll
            for (int dx = 0; dx < 3; dx++) {
                int yy = y + dy - 1, xx = x + dx - 1;
                bool ok = (unsigned)yy < 64u && (unsigned)xx < 64u;
                off[dy * 3 + dx] = ok ? yy * 64 + xx : 0;
                msk[dy * 3 + dx] = ok ? 1.f : 0.f;
            }
        __half h8[DWC];
#pragma unroll
        for (int ch = 0; ch < DWC; ch++) {
            const float* pl = S + ch * HWP;
            float s = 0.f;
#pragma unroll
            for (int t = 0; t < 9; t++)
                s = fmaf(w[ch][t], pl[off[t]] * msk[t], s);
            s = s * sc[ch] + bi[ch];
            s = s * (1.f / (1.f + __expf(-s)));
            h8[ch] = __float2half_rn(s * XSCALE);
        }
        *(uint4*)&outp[(size_t)p * CC] = *(uint4*)h8;
    }
}

// ---------------------------------------------------------------------------
// Launch. setup_inputs() dict order:
//   0:x 1:w1 2:w2 3:w3 4:g1 5:b1 6:m1 7:v1 8:g2 9:b2 10:m2 11:v2 12:g3 13:b3 14:m3 15:v3
// ---------------------------------------------------------------------------
extern "C" void kernel_launch(void* const* d_in, const int* in_sizes, int n_in,
                              void* d_out, int out_size)
{
    const float* x  = (const float*)d_in[0];
    const float* w1 = (const float*)d_in[1];
    const float* w2 = (const float*)d_in[2];
    const float* w3 = (const float*)d_in[3];
    const float* g1 = (const float*)d_in[4];
    const float* b1 = (const float*)d_in[5];
    const float* m1 = (const float*)d_in[6];
    const float* v1 = (const float*)d_in[7];
    const float* g2 = (const float*)d_in[8];
    const float* b2 = (const float*)d_in[9];
    const float* m2 = (const float*)d_in[10];
    const float* v2 = (const float*)d_in[11];
    const float* g3 = (const float*)d_in[12];
    const float* b3 = (const float*)d_in[13];
    const float* m3 = (const float*)d_in[14];
    const float* v3 = (const float*)d_in[15];
    float* out = (float*)d_out;

    if (!(in_sizes[1] == CC * CC && in_sizes[2] == CC * 9 && in_sizes[3] == CC * CC)) {
        const float* big[2] = {nullptr, nullptr}; int nbig = 0;
        const float* small9216 = nullptr;
        const float* perch[12]; int nper = 0;
        for (int i = 1; i < n_in; i++) {
            if (in_sizes[i] == CC * CC && nbig < 2) big[nbig++] = (const float*)d_in[i];
            else if (in_sizes[i] == CC * 9) small9216 = (const float*)d_in[i];
            else if (in_sizes[i] == CC && nper < 12) perch[nper++] = (const float*)d_in[i];
        }
        w1 = big[0]; w3 = big[1]; w2 = small9216;
        g1 = perch[0]; b1 = perch[1]; m1 = perch[2];  v1 = perch[3];
        g2 = perch[4]; b2 = perch[5]; m2 = perch[6];  v2 = perch[7];
        g3 = perch[8]; b3 = perch[9]; m3 = perch[10]; v3 = perch[11];
    }

    float *p_y1, *p_y2;
    __half *p_w1h, *p_w3h, *p_bh;
    cudaGetSymbolAddress((void**)&p_y1, g_y1);
    cudaGetSymbolAddress((void**)&p_y2, g_y2);
    cudaGetSymbolAddress((void**)&p_w1h, g_w1h);
    cudaGetSymbolAddress((void**)&p_w3h, g_w3h);
    cudaGetSymbolAddress((void**)&p_bh, g_bh);

    cudaFuncSetAttribute(gemm_mma_kernel,
                         cudaFuncAttributeMaxDynamicSharedMemorySize, SMEM_TOT);
    cudaFuncSetAttribute(dwconv_t_kernel,
                         cudaFuncAttributeMaxDynamicSharedMemorySize, DW_SMEM);

    dim3 tgrid(HWP / 32, CC / 64, BB);
    dim3 ggrid(HWP / BN, CC / BM, BB);     // (32, 8, 8)
    dim3 dgrid(CC / DWC, BB);              // (128, 8)

    convert_w2_kernel<<<(CC * CC + 511) / 512, 512>>>(w1, w3, p_w1h, p_w3h);
    transpose_cvt_kernel<<<tgrid, 256>>>(x, p_bh);
    gemm_mma_kernel<<<ggrid, 256, SMEM_TOT>>>(p_w1h, p_bh,
                                              g1, b1, m1, v1, nullptr, p_y1);
    attn_kernel<<<BB * NHD * HH, 256>>>(p_y1, p_y2);
    dwconv_t_kernel<<<dgrid, 256, DW_SMEM>>>(p_y2, w2, g2, b2, m2, v2, p_bh);
    gemm_mma_kernel<<<ggrid, 256, SMEM_TOT>>>(p_w3h, p_bh,
                                              g3, b3, m3, v3, x, out);
}

// round 11
// speedup vs baseline: 1.4558x; 1.0809x over previous
#include <cuda_runtime.h>
#include <cuda_fp16.h>
#include <cstdint>

// Problem constants
#define BB   8
#define CC   1024
#define HH   64
#define WW   64
#define NHD  16
#define HD   64
#define HWP  4096
#define CHW  (CC * HWP)
#define EPSB 1e-3f

// Scale folding: W stored x2^14, X stored x2^10, epilogue multiplies 2^-24.
#define WSCALE 16384.0f
#define XSCALE 1024.0f
#define INV_S  5.9604644775390625e-8f   // 2^-24

// GEMM tiling (R8-proven: 128x128, BK=64, 2-stage, 2 CTAs/SM)
#define BM   128
#define BN   128
#define BKE  64
#define LDT  72              // padded SMEM row (elems) = 144B
#define NKT  (CC / BKE)      // 16

#define TILE_B   (128 * LDT * 2)          // 18432 B
#define STAGE_B  (2 * TILE_B)
#define SMEM_TOT (2 * STAGE_B)            // 73728 B -> 2 CTAs/SM

// dwconv fused kernel (fp16 input)
#define DWC  8
#define DW_SMEM_H (DWC * HWP * 2)         // 65536 B -> 2 CTAs/SM

// attention
#define LDP  72              // fp16 row pad for ldmatrix tiles

// ---------------------------------------------------------------------------
// Scratch (device globals)
// ---------------------------------------------------------------------------
__device__ __half g_y1h[BB * CHW];       // conv1 output (fp16)
__device__ __half g_y2h[BB * CHW];       // attention output (fp16)
__device__ __half g_w1h[CC * CC];
__device__ __half g_w3h[CC * CC];
__device__ __half g_bh[BB * HWP * CC];   // transposed activations [b][p][ci]

// ---------------------------------------------------------------------------
// PTX helpers
// ---------------------------------------------------------------------------
__device__ __forceinline__ uint32_t smem_u32(const void* p) {
    uint32_t a;
    asm("{ .reg .u64 t; cvta.to.shared.u64 t, %1; cvt.u32.u64 %0, t; }" : "=r"(a) : "l"(p));
    return a;
}
__device__ __forceinline__ void cp_async16(uint32_t saddr, const void* gaddr) {
    asm volatile("cp.async.cg.shared.global [%0], [%1], 16;" :: "r"(saddr), "l"(gaddr));
}
__device__ __forceinline__ void cp_commit() {
    asm volatile("cp.async.commit_group;" ::: "memory");
}
template <int N>
__device__ __forceinline__ void cp_wait() {
    asm volatile("cp.async.wait_group %0;" :: "n"(N) : "memory");
}
__device__ __forceinline__ void ldmx4(uint32_t* r, uint32_t addr) {
    asm volatile("ldmatrix.sync.aligned.m8n8.x4.shared.b16 {%0,%1,%2,%3}, [%4];"
                 : "=r"(r[0]), "=r"(r[1]), "=r"(r[2]), "=r"(r[3]) : "r"(addr));
}
__device__ __forceinline__ void mma16816(float* c, const uint32_t* a,
                                         uint32_t b0, uint32_t b1) {
    asm volatile(
        "mma.sync.aligned.m16n8k16.row.col.f32.f16.f16.f32 "
        "{%0,%1,%2,%3}, {%4,%5,%6,%7}, {%8,%9}, {%0,%1,%2,%3};"
        : "+f"(c[0]), "+f"(c[1]), "+f"(c[2]), "+f"(c[3])
        : "r"(a[0]), "r"(a[1]), "r"(a[2]), "r"(a[3]), "r"(b0), "r"(b1));
}

// ---------------------------------------------------------------------------
// Converters
// ---------------------------------------------------------------------------
__global__ void convert_w2_kernel(const float* __restrict__ W1,
                                  const float* __restrict__ W3,
                                  __half* __restrict__ O1,
                                  __half* __restrict__ O3)
{
    int i = blockIdx.x * blockDim.x + threadIdx.x;
    if (i < CC * CC) {
        O1[i] = __float2half_rn(W1[i] * WSCALE);
        O3[i] = __float2half_rn(W3[i] * WSCALE);
    }
}

// Transpose+convert: X fp32 [b][ci][p] -> fp16 [b][p][ci], scaled by XSCALE.
__global__ __launch_bounds__(256)
void transpose_cvt_kernel(const float* __restrict__ X,
                          __half* __restrict__ Th)
{
    __shared__ float t[64][33];
    const int p0 = blockIdx.x * 32;
    const int c0 = blockIdx.y * 64;
    const int b  = blockIdx.z;
    const int tid = threadIdx.x;

    const float* Xb = X + (size_t)b * CHW;
#pragma unroll
    for (int j = 0; j < 8; j++) {
        int i = j * 256 + tid;
        int r = i >> 5, cl = i & 31;
        t[r][cl] = Xb[(size_t)(c0 + r) * HWP + p0 + cl];
    }
    __syncthreads();

    __half* Tp = Th + (size_t)b * HWP * CC;
    const int cp = tid & 31;
#pragma unroll
    for (int j = 0; j < 4; j++) {
        int p = (tid >> 5) + j * 8;
        __half2 v = __floats2half2_rn(t[2 * cp][p] * XSCALE,
                                      t[2 * cp + 1][p] * XSCALE);
        *(__half2*)&Tp[(size_t)(p0 + p) * CC + c0 + 2 * cp] = v;
    }
}

// ---------------------------------------------------------------------------
// Warp-MMA fp16 GEMM + BN + SiLU. HALF_OUT: fp16 store, no residual.
// ---------------------------------------------------------------------------
template <bool HALF_OUT>
__global__ __launch_bounds__(256, 2)
void gemm_mma_kernel(const __half* __restrict__ Ah,
                     const __half* __restrict__ Bh_,
                     const float* __restrict__ gam,
                     const float* __restrict__ bet,
                     const float* __restrict__ mu,
                     const float* __restrict__ var,
                     const float* __restrict__ res,
                     void* __restrict__ outv)
{
    extern __shared__ char smem[];
    const uint32_t sb = smem_u32(smem);

    const int tid  = threadIdx.x;
    const int warp = tid >> 5, lane = tid & 31;
    const int warp_m = warp >> 2;
    const int warp_n = warp & 3;

    const int n0 = blockIdx.x * BN;
    const int m0 = blockIdx.y * BM;
    const int bz = blockIdx.z;
    const __half* Bh = Bh_ + (size_t)bz * HWP * CC;

    float acc[4][4][4];
#pragma unroll
    for (int i = 0; i < 4; i++)
#pragma unroll
        for (int j = 0; j < 4; j++)
#pragma unroll
            for (int q = 0; q < 4; q++) acc[i][j][q] = 0.f;

    const __half* apt[4];
    const __half* bpt[4];
    uint32_t soff[4];
#pragma unroll
    for (int j = 0; j < 4; j++) {
        int rc = tid + j * 256;
        int row = rc >> 3, c = (rc & 7) * 8;
        soff[j] = (row * LDT + c) * 2;
        apt[j] = Ah + (size_t)(m0 + row) * CC + c;
        bpt[j] = Bh + (size_t)(n0 + row) * CC + c;
    }

    auto stage = [&](int it) {
        const uint32_t st = sb + (it & 1) * STAGE_B;
        const int kt = it * BKE;
#pragma unroll
        for (int j = 0; j < 4; j++) {
            cp_async16(st + soff[j], apt[j] + kt);
            cp_async16(st + TILE_B + soff[j], bpt[j] + kt);
        }
        cp_commit();
    };

    const int lr = lane & 15;
    const int lh = (lane >> 4) * 8;

    stage(0);

    for (int it = 0; it < NKT; it++) {
        if (it + 1 < NKT) {
            stage(it + 1);
            cp_wait<1>();
        } else {
            cp_wait<0>();
        }
        __syncthreads();

        const uint32_t st = sb + (it & 1) * STAGE_B;
#pragma unroll
        for (int kh = 0; kh < 4; kh++) {
            const int k16 = kh * 16;
            uint32_t af[4][4];
#pragma unroll
            for (int mt = 0; mt < 4; mt++)
                ldmx4(af[mt], st + ((warp_m * 64 + mt * 16 + lr) * LDT + k16 + lh) * 2);
            uint32_t bf[2][4];
#pragma unroll
            for (int nt2 = 0; nt2 < 2; nt2++)
                ldmx4(bf[nt2], st + TILE_B +
                      ((warp_n * 32 + nt2 * 16 + lr) * LDT + k16 + lh) * 2);
#pragma unroll
            for (int mt = 0; mt < 4; mt++)
#pragma unroll
                for (int nt = 0; nt < 4; nt++)
                    mma16816(acc[mt][nt], af[mt],
                             bf[nt >> 1][nt & 1], bf[nt >> 1][(nt & 1) + 2]);
        }
        __syncthreads();
    }

    const int qrow = lane >> 2;
    const int qcol = (lane & 3) * 2;
#pragma unroll
    for (int mt = 0; mt < 4; mt++) {
#pragma unroll
        for (int half = 0; half < 2; half++) {
            const int co = m0 + warp_m * 64 + mt * 16 + qrow + half * 8;
            const float sc0 = gam[co] * rsqrtf(var[co] + EPSB);
            const float bi = bet[co] - mu[co] * sc0;
            const float sc = sc0 * INV_S;
            const size_t rbase = (size_t)bz * CHW + (size_t)co * HWP + n0 + warp_n * 32;
#pragma unroll
            for (int nt = 0; nt < 4; nt++) {
                const int nn = nt * 8 + qcol;
                float y0 = acc[mt][nt][half * 2 + 0] * sc + bi;
                float y1 = acc[mt][nt][half * 2 + 1] * sc + bi;
                y0 = y0 * (1.f / (1.f + __expf(-y0)));
                y1 = y1 * (1.f / (1.f + __expf(-y1)));
                if (HALF_OUT) {
                    __half* orow = (__half*)outv + rbase;
                    *(__half2*)&orow[nn] = __floats2half2_rn(y0, y1);
                } else {
                    float* orow = (float*)outv + rbase;
                    if (res) {
                        const float* rrow = res + rbase;
                        y0 += rrow[nn];
                        y1 += rrow[nn + 1];
                    }
                    *(float2*)&orow[nn] = make_float2(y0, y1);
                }
            }
        }
    }
}

// ---------------------------------------------------------------------------
// K2: per-(b,nh,h) softmax-attention. fp16 in/out; softmax fp32; MMA fp16.
//   att[w][v] = sum_k P[w][k] * A[v][k]
// ---------------------------------------------------------------------------
__global__ __launch_bounds__(256)
void attn_kernel(const __half* __restrict__ Y1, __half* __restrict__ Y2)
{
    const int bid = blockIdx.x;
    const int h  = bid & 63;
    const int nh = (bid >> 6) & 15;
    const int b  = bid >> 10;

    const __half* basep = Y1 + (size_t)b * CHW + (size_t)(nh * HD) * HWP + h * WW;

    __shared__ __half Ahh[64][LDP];    // A[w][k]
    __shared__ __half Ph[64][LDP];     // P[w][k], reused for output staging

    const int tid = threadIdx.x;
    const int lane = tid & 31, warp = tid >> 5;

    // load + transpose: A[w][k] = y1h[k][w]
#pragma unroll
    for (int it = 0; it < 16; it++) {
        int idx = it * 256 + tid;
        int k = idx >> 6, w = idx & 63;
        Ahh[w][k] = basep[(size_t)k * HWP + w];
    }
    __syncthreads();

    // softmax rows (fp32 math from fp16 input), P -> fp16
#pragma unroll
    for (int r = 0; r < 8; r++) {
        int row = warp * 8 + r;
        float x0 = __half2float(Ahh[row][lane]);
        float x1 = __half2float(Ahh[row][lane + 32]);
        float mx = fmaxf(x0, x1);
#pragma unroll
        for (int o = 16; o > 0; o >>= 1) mx = fmaxf(mx, __shfl_xor_sync(0xffffffffu, mx, o));
        float e0 = __expf(x0 - mx), e1 = __expf(x1 - mx);
        float s = e0 + e1;
#pragma unroll
        for (int o = 16; o > 0; o >>= 1) s += __shfl_xor_sync(0xffffffffu, s, o);
        float inv = 1.f / s;
        Ph[row][lane]      = __float2half_rn(e0 * inv);
        Ph[row][lane + 32] = __float2half_rn(e1 * inv);
    }
    __syncthreads();

    // MMA: warp tile 16(m=w) x 32(n=v), K=64
    const uint32_t ph = smem_u32(Ph);
    const uint32_t ah = smem_u32(Ahh);
    const int m0 = (warp & 3) * 16;
    const int nw0 = (warp >> 2) * 32;
    const int lr = lane & 15;
    const int lh = (lane >> 4) * 8;

    float acc[4][4];
#pragma unroll
    for (int i = 0; i < 4; i++)
#pragma unroll
        for (int q = 0; q < 4; q++) acc[i][q] = 0.f;

#pragma unroll
    for (int kh = 0; kh < 4; kh++) {
        const int k16 = kh * 16;
        uint32_t a[4];
        ldmx4(a, ph + ((m0 + lr) * LDP + k16 + lh) * 2);
        uint32_t bf[2][4];
#pragma unroll
        for (int g = 0; g < 2; g++)
            ldmx4(bf[g], ah + ((nw0 + g * 16 + lr) * LDP + k16 + lh) * 2);
#pragma unroll
        for (int nt = 0; nt < 4; nt++)
            mma16816(acc[nt], a, bf[nt >> 1][nt & 1], bf[nt >> 1][(nt & 1) + 2]);
    }
    __syncthreads();

    // stage att transposed in Ph: Ph[v][w] = att[w][v]  (fp16)
    const int qrow = lane >> 2;
    const int qcol = (lane & 3) * 2;
#pragma unroll
    for (int nt = 0; nt < 4; nt++)
#pragma unroll
        for (int half = 0; half < 2; half++) {
            int w = m0 + qrow + half * 8;
            int v = nw0 + nt * 8 + qcol;
            Ph[v][w]     = __float2half_rn(acc[nt][half * 2 + 0]);
            Ph[v + 1][w] = __float2half_rn(acc[nt][half * 2 + 1]);
        }
    __syncthreads();

    __half* outb = Y2 + (size_t)b * CHW + (size_t)(nh * HD) * HWP + h * WW;
#pragma unroll
    for (int it = 0; it < 16; it++) {
        int idx = it * 256 + tid;
        int v = idx >> 6, w = idx & 63;
        outb[(size_t)v * HWP + w] = Ph[v][w];
    }
}

// ---------------------------------------------------------------------------
// K3 fused: depthwise 3x3 + BN + SiLU + transpose + fp16 convert. fp16 input.
// ---------------------------------------------------------------------------
__global__ __launch_bounds__(256)
void dwconv_t_kernel(const __half* __restrict__ X,
                     const float* __restrict__ W2,
                     const float* __restrict__ gam,
                     const float* __restrict__ bet,
                     const float* __restrict__ mu,
                     const float* __restrict__ var,
                     __half* __restrict__ Th)
{
    extern __shared__ __half Sh[];     // DWC * 4096 halves
    const int c0 = blockIdx.x * DWC;
    const int b  = blockIdx.y;
    const int tid = threadIdx.x;

    // coalesced bulk copy of 8 contiguous fp16 planes (64KB)
    const uint4* src = (const uint4*)(X + ((size_t)b * CC + c0) * HWP);
    uint4* dst = (uint4*)Sh;
#pragma unroll
    for (int j = 0; j < 16; j++)
        dst[j * 256 + tid] = src[j * 256 + tid];

    float w[DWC][9], sc[DWC], bi[DWC];
#pragma unroll
    for (int ch = 0; ch < DWC; ch++) {
        const int c = c0 + ch;
#pragma unroll
        for (int k = 0; k < 9; k++) w[ch][k] = W2[c * 9 + k];
        const float s0 = gam[c] * rsqrtf(var[c] + EPSB);
        sc[ch] = s0;
        bi[ch] = bet[c] - mu[c] * s0;
    }
    __syncthreads();

    __half* outp = Th + (size_t)b * HWP * CC + c0;
#pragma unroll 2
    for (int k = 0; k < 16; k++) {
        const int p = k * 256 + tid;
        const int y = p >> 6, x = p & 63;
        int off[9];
        float msk[9];
#pragma unroll
        for (int dy = 0; dy < 3; dy++)
#pragma unroll
            for (int dx = 0; dx < 3; dx++) {
                int yy = y + dy - 1, xx = x + dx - 1;
                bool ok = (unsigned)yy < 64u && (unsigned)xx < 64u;
                off[dy * 3 + dx] = ok ? yy * 64 + xx : 0;
                msk[dy * 3 + dx] = ok ? 1.f : 0.f;
            }
        __half h8[DWC];
#pragma unroll
        for (int ch = 0; ch < DWC; ch++) {
            const __half* pl = Sh + ch * HWP;
            float s = 0.f;
#pragma unroll
            for (int t = 0; t < 9; t++)
                s = fmaf(w[ch][t], __half2float(pl[off[t]]) * msk[t], s);
            s = s * sc[ch] + bi[ch];
            s = s * (1.f / (1.f + __expf(-s)));
            h8[ch] = __float2half_rn(s * XSCALE);
        }
        *(uint4*)&outp[(size_t)p * CC] = *(uint4*)h8;
    }
}

// ---------------------------------------------------------------------------
// Launch. setup_inputs() dict order:
//   0:x 1:w1 2:w2 3:w3 4:g1 5:b1 6:m1 7:v1 8:g2 9:b2 10:m2 11:v2 12:g3 13:b3 14:m3 15:v3
// ---------------------------------------------------------------------------
extern "C" void kernel_launch(void* const* d_in, const int* in_sizes, int n_in,
                              void* d_out, int out_size)
{
    const float* x  = (const float*)d_in[0];
    const float* w1 = (const float*)d_in[1];
    const float* w2 = (const float*)d_in[2];
    const float* w3 = (const float*)d_in[3];
    const float* g1 = (const float*)d_in[4];
    const float* b1 = (const float*)d_in[5];
    const float* m1 = (const float*)d_in[6];
    const float* v1 = (const float*)d_in[7];
    const float* g2 = (const float*)d_in[8];
    const float* b2 = (const float*)d_in[9];
    const float* m2 = (const float*)d_in[10];
    const float* v2 = (const float*)d_in[11];
    const float* g3 = (const float*)d_in[12];
    const float* b3 = (const float*)d_in[13];
    const float* m3 = (const float*)d_in[14];
    const float* v3 = (const float*)d_in[15];
    float* out = (float*)d_out;

    if (!(in_sizes[1] == CC * CC && in_sizes[2] == CC * 9 && in_sizes[3] == CC * CC)) {
        const float* big[2] = {nullptr, nullptr}; int nbig = 0;
        const float* small9216 = nullptr;
        const float* perch[12]; int nper = 0;
        for (int i = 1; i < n_in; i++) {
            if (in_sizes[i] == CC * CC && nbig < 2) big[nbig++] = (const float*)d_in[i];
            else if (in_sizes[i] == CC * 9) small9216 = (const float*)d_in[i];
            else if (in_sizes[i] == CC && nper < 12) perch[nper++] = (const float*)d_in[i];
        }
        w1 = big[0]; w3 = big[1]; w2 = small9216;
        g1 = perch[0]; b1 = perch[1]; m1 = perch[2];  v1 = perch[3];
        g2 = perch[4]; b2 = perch[5]; m2 = perch[6];  v2 = perch[7];
        g3 = perch[8]; b3 = perch[9]; m3 = perch[10]; v3 = perch[11];
    }

    __half *p_y1h, *p_y2h, *p_w1h, *p_w3h, *p_bh;
    cudaGetSymbolAddress((void**)&p_y1h, g_y1h);
    cudaGetSymbolAddress((void**)&p_y2h, g_y2h);
    cudaGetSymbolAddress((void**)&p_w1h, g_w1h);
    cudaGetSymbolAddress((void**)&p_w3h, g_w3h);
    cudaGetSymbolAddress((void**)&p_bh, g_bh);

    cudaFuncSetAttribute(gemm_mma_kernel<true>,
                         cudaFuncAttributeMaxDynamicSharedMemorySize, SMEM_TOT);
    cudaFuncSetAttribute(gemm_mma_kernel<false>,
                         cudaFuncAttributeMaxDynamicSharedMemorySize, SMEM_TOT);
    cudaFuncSetAttribute(dwconv_t_kernel,
                         cudaFuncAttributeMaxDynamicSharedMemorySize, DW_SMEM_H);

    dim3 tgrid(HWP / 32, CC / 64, BB);
    dim3 ggrid(HWP / BN, CC / BM, BB);     // (32, 8, 8)
    dim3 dgrid(CC / DWC, BB);              // (128, 8)

    convert_w2_kernel<<<(CC * CC + 511) / 512, 512>>>(w1, w3, p_w1h, p_w3h);
    transpose_cvt_kernel<<<tgrid, 256>>>(x, p_bh);
    gemm_mma_kernel<true><<<ggrid, 256, SMEM_TOT>>>(p_w1h, p_bh,
                                                    g1, b1, m1, v1, nullptr, p_y1h);
    attn_kernel<<<BB * NHD * HH, 256>>>(p_y1h, p_y2h);
    dwconv_t_kernel<<<dgrid, 256, DW_SMEM_H>>>(p_y2h, w2, g2, b2, m2, v2, p_bh);
    gemm_mma_kernel<false><<<ggrid, 256, SMEM_TOT>>>(p_w3h, p_bh,
                                                     g3, b3, m3, v3, x, out);
}